// round 1
// baseline (speedup 1.0000x reference)
#include <cuda_runtime.h>
#include <cuda_bf16.h>

// scratch for the 4-channel logits on the small 14^3 grid (43 KB)
__device__ float g_z[4 * 14 * 14 * 14];

// ---------------------------------------------------------------------------
// Kernel 1: 1x1x1 conv on the small grid. z[o][v] = b[o] + sum_c W[o][c]*x[c][v]
// 10976 outputs, each a 32-wide dot product. Trivial cost.
// ---------------------------------------------------------------------------
__global__ void conv_small_kernel(const float* __restrict__ x,
                                  const float* __restrict__ W,
                                  const float* __restrict__ b) {
    int idx = blockIdx.x * blockDim.x + threadIdx.x;
    if (idx >= 4 * 2744) return;
    int o = idx / 2744;
    int v = idx - o * 2744;
    float acc = b[o];
    const float* wrow = W + o * 32;
#pragma unroll
    for (int c = 0; c < 32; c++) {
        acc = fmaf(wrow[c], x[c * 2744 + v], acc);
    }
    g_z[idx] = acc;
}

// ---------------------------------------------------------------------------
// Kernel 2: per output row (d, h): cooperatively bilinear-lerp (d,h) into a
// 14-wide 4-channel line in smem, then each thread handles one w: lerp,
// softmax over 4 classes, 4 coalesced stores into the channel planes.
// ---------------------------------------------------------------------------
__global__ __launch_bounds__(224) void upsample_softmax_kernel(float* __restrict__ out) {
    __shared__ float4 gs[14];  // gs[iw] = 4-channel bilinear-lerped value

    const int h = blockIdx.x;
    const int d = blockIdx.y;
    const int tid = threadIdx.x;

    const float scale = 13.0f / 223.0f;  // align_corners=True: (in-1)/(out-1)

    // d / h interpolation params (same for the whole block; cheap to recompute)
    float pd = (float)d * scale;
    int id0 = (int)pd; if (id0 > 12) id0 = 12;
    float wd = pd - (float)id0;
    float ph = (float)h * scale;
    int ih0 = (int)ph; if (ih0 > 12) ih0 = 12;
    float wh = ph - (float)ih0;

    // cooperative fill: 56 values = 14 iw positions x 4 channels
    if (tid < 56) {
        int iw = tid >> 2;
        int c  = tid & 3;
        const float* zb = g_z + c * 2744;
        int base = (id0 * 14 + ih0) * 14 + iw;
        float z00 = zb[base];
        float z01 = zb[base + 14];    // ih0+1
        float z10 = zb[base + 196];   // id0+1
        float z11 = zb[base + 196 + 14];
        float a0 = z00 + wh * (z01 - z00);
        float a1 = z10 + wh * (z11 - z10);
        ((float*)gs)[iw * 4 + c] = a0 + wd * (a1 - a0);
    }
    __syncthreads();

    // per-thread: one output w position
    const int w = tid;
    float pw = (float)w * scale;
    int iw0 = (int)pw; if (iw0 > 12) iw0 = 12;
    float ww = pw - (float)iw0;

    float4 A = gs[iw0];
    float4 B = gs[iw0 + 1];
    float z0 = A.x + ww * (B.x - A.x);
    float z1 = A.y + ww * (B.y - A.y);
    float z2 = A.z + ww * (B.z - A.z);
    float z3 = A.w + ww * (B.w - A.w);

    // softmax over the 4 classes
    float m = fmaxf(fmaxf(z0, z1), fmaxf(z2, z3));
    float e0 = __expf(z0 - m);
    float e1 = __expf(z1 - m);
    float e2 = __expf(z2 - m);
    float e3 = __expf(z3 - m);
    float r = __frcp_rn(e0 + e1 + e2 + e3);

    const int PLANE = 224 * 224 * 224;
    int idx = (d * 224 + h) * 224 + w;
    out[idx]             = e0 * r;
    out[idx + PLANE]     = e1 * r;
    out[idx + 2 * PLANE] = e2 * r;
    out[idx + 3 * PLANE] = e3 * r;
}

extern "C" void kernel_launch(void* const* d_in, const int* in_sizes, int n_in,
                              void* d_out, int out_size) {
    const float* x = (const float*)d_in[0];  // [1,32,14,14,14]
    const float* W = (const float*)d_in[1];  // [4,32]
    const float* b = (const float*)d_in[2];  // [4]
    float* out = (float*)d_out;              // [1,4,224,224,224]

    conv_small_kernel<<<(4 * 2744 + 255) / 256, 256>>>(x, W, b);

    dim3 grid(224, 224);  // (h, d)
    upsample_softmax_kernel<<<grid, 224>>>(out);
}

// round 2
// speedup vs baseline: 1.1908x; 1.1908x over previous
#include <cuda_runtime.h>
#include <cuda_bf16.h>

// scratch for the 4-channel logits (pre-scaled by log2(e)) on the 14^3 grid
__device__ float g_z[4 * 14 * 14 * 14];

#define LOG2E 1.4426950408889634f

// ---------------------------------------------------------------------------
// Kernel 1: 1x1x1 conv on the small grid, output pre-multiplied by log2(e) so
// the big kernel can use raw exp2 (single MUFU.EX2 per element).
// ---------------------------------------------------------------------------
__global__ void conv_small_kernel(const float* __restrict__ x,
                                  const float* __restrict__ W,
                                  const float* __restrict__ b) {
    int idx = blockIdx.x * blockDim.x + threadIdx.x;
    if (idx >= 4 * 2744) return;
    int o = idx / 2744;
    int v = idx - o * 2744;
    float acc = b[o];
    const float* wrow = W + o * 32;
#pragma unroll
    for (int c = 0; c < 32; c++) {
        acc = fmaf(wrow[c], x[c * 2744 + v], acc);
    }
    g_z[idx] = acc * LOG2E;
}

// ---------------------------------------------------------------------------
// Kernel 2: block = (56, 4) threads handles 4 output rows (same d, 4
// consecutive h). Fill phase: each ty-row bilinear-lerps its 14-wide
// 4-channel line into smem; the 224 threads also build a per-w (iw0, ww)
// table. Main phase: each thread produces 4 consecutive w voxels and writes
// one float4 per channel plane (4x STG.128).
// Softmax without max-subtraction (logits are O(1), exp2-domain, safe) using
// rcp.approx for the normalization.
// ---------------------------------------------------------------------------
__global__ __launch_bounds__(224) void upsample_softmax_kernel(float* __restrict__ out) {
    __shared__ float4 gs[4][14];   // per-row, per-iw: 4-channel lerped (log2-domain)
    __shared__ float  sww[224];
    __shared__ int    siw[224];

    const int tx = threadIdx.x;          // 0..55
    const int ty = threadIdx.y;          // 0..3
    const int d  = blockIdx.y;
    const int h  = blockIdx.x * 4 + ty;
    const float scale = 13.0f / 223.0f;  // align_corners=True

    float pd = (float)d * scale;
    int id0 = (int)pd; if (id0 > 12) id0 = 12;
    float wd = pd - (float)id0;
    float ph = (float)h * scale;
    int ih0 = (int)ph; if (ih0 > 12) ih0 = 12;
    float wh = ph - (float)ih0;

    // fill this row's 56 floats (14 iw x 4 ch)
    {
        int iw = tx >> 2, c = tx & 3;
        const float* zb = g_z + c * 2744;
        int base = (id0 * 14 + ih0) * 14 + iw;
        float z00 = zb[base];
        float z01 = zb[base + 14];
        float z10 = zb[base + 196];
        float z11 = zb[base + 210];
        float a0 = fmaf(wh, z01 - z00, z00);
        float a1 = fmaf(wh, z11 - z10, z10);
        ((float*)gs[ty])[tx] = fmaf(wd, a1 - a0, a0);
    }
    // fill per-w interpolation table (224 entries, one per thread)
    {
        int w = ty * 56 + tx;
        float pw = (float)w * scale;
        int iw0 = (int)pw; if (iw0 > 12) iw0 = 12;
        siw[w] = iw0;
        sww[w] = pw - (float)iw0;
    }
    __syncthreads();

    const int w0 = tx * 4;
    float r0[4], r1[4], r2[4], r3[4];

#pragma unroll
    for (int k = 0; k < 4; k++) {
        int w = w0 + k;
        int iw = siw[w];
        float ww = sww[w];
        float4 A = gs[ty][iw];
        float4 B = gs[ty][iw + 1];
        // lerp in log2 domain
        float z0 = fmaf(ww, B.x - A.x, A.x);
        float z1 = fmaf(ww, B.y - A.y, A.y);
        float z2 = fmaf(ww, B.z - A.z, A.z);
        float z3 = fmaf(ww, B.w - A.w, A.w);
        float e0 = exp2f(z0);
        float e1 = exp2f(z1);
        float e2 = exp2f(z2);
        float e3 = exp2f(z3);
        float s = (e0 + e1) + (e2 + e3);
        float rr;
        asm("rcp.approx.f32 %0, %1;" : "=f"(rr) : "f"(s));
        r0[k] = e0 * rr;
        r1[k] = e1 * rr;
        r2[k] = e2 * rr;
        r3[k] = e3 * rr;
    }

    const int PLANE4 = (224 * 224 * 224) >> 2;
    int idx4 = (((d * 224 + h) * 224 + w0) >> 2);
    float4* o4 = (float4*)out;
    o4[idx4]              = make_float4(r0[0], r0[1], r0[2], r0[3]);
    o4[idx4 + PLANE4]     = make_float4(r1[0], r1[1], r1[2], r1[3]);
    o4[idx4 + 2 * PLANE4] = make_float4(r2[0], r2[1], r2[2], r2[3]);
    o4[idx4 + 3 * PLANE4] = make_float4(r3[0], r3[1], r3[2], r3[3]);
}

extern "C" void kernel_launch(void* const* d_in, const int* in_sizes, int n_in,
                              void* d_out, int out_size) {
    const float* x = (const float*)d_in[0];  // [1,32,14,14,14]
    const float* W = (const float*)d_in[1];  // [4,32]
    const float* b = (const float*)d_in[2];  // [4]
    float* out = (float*)d_out;              // [1,4,224,224,224]

    conv_small_kernel<<<(4 * 2744 + 255) / 256, 256>>>(x, W, b);

    dim3 block(56, 4);
    dim3 grid(56, 224);  // (h-group of 4, d)
    upsample_softmax_kernel<<<grid, block>>>(out);
}